// round 17
// baseline (speedup 1.0000x reference)
#include <cuda_runtime.h>
#include <cuda_fp16.h>
#include <cstdint>

#define NROWS 8192
#define DIM 128
#define KSPLIT 4
#define KSLICE (NROWS / KSPLIT)   // 2048
#define ZROWS 8                   // j-rows per z block
#define ZBLK (NROWS / ZROWS)      // 1024 z blocks

__device__ float g_dis[NROWS];
__device__ __half g_yh[(size_t)NROWS * DIM];          // Y fp16 k-major (reduce; NO dis)
__device__ __half g_yt[(size_t)DIM * NROWS];          // Y^T fp16 n-major (GEMM B; NO dis)
__device__ __half g_parth[KSPLIT][(size_t)NROWS * DIM];  // split-K partials fp16

static __device__ __forceinline__ uint32_t s2u(const void* p) {
    uint32_t a;
    asm("{ .reg .u64 t; cvta.to.shared.u64 t, %1; cvt.u32.u64 %0, t; }" : "=r"(a) : "l"(p));
    return a;
}

// ===================== kernel 1: FUSED prep: z-blocks (first) + rowsum blocks =====================
// Reg cap 32 keeps rowsum at 8 CTAs/SM; z branch now sized (acc[4]) to FIT the cap, no spills.
__global__ void __launch_bounds__(256, 8) prep_kernel(const float4* __restrict__ A4,
                                                      const float* __restrict__ X,
                                                      const float* __restrict__ W) {
    __shared__ float4 Xs4[ZROWS * 32];    // 4KB (z path)
    __shared__ float T[128][9];           // 4.6KB transpose staging (z path)
    __shared__ float ws[8];               // rowsum path
    int tid = threadIdx.x;

    if (blockIdx.x < ZBLK) {
        // ---- z: Y = X W^T (no dis), fp16 both layouts ----
        int j0 = blockIdx.x * ZROWS;
        const float4* Xg = reinterpret_cast<const float4*>(X) + (size_t)j0 * 32;
        Xs4[tid] = Xg[tid];               // 256 float4 = 8 rows x 128 floats
        __syncthreads();

        int n = tid & 127, half = tid >> 7;   // half selects 4-row group
        float acc[4];
        #pragma unroll
        for (int jj = 0; jj < 4; jj++) acc[jj] = 0.f;

        const float4* Wr = reinterpret_cast<const float4*>(W) + (size_t)n * 32;
        #pragma unroll 4
        for (int c4 = 0; c4 < 32; c4++) {
            float4 w = __ldg(Wr + c4);
            #pragma unroll
            for (int jj = 0; jj < 4; jj++) {
                float4 x = Xs4[(half * 4 + jj) * 32 + c4];
                acc[jj] += x.x * w.x + x.y * w.y + x.z * w.z + x.w * w.w;
            }
        }
        #pragma unroll
        for (int jj = 0; jj < 4; jj++) {
            int j = j0 + half * 4 + jj;
            T[n][half * 4 + jj] = acc[jj];
            g_yh[(size_t)j * DIM + n] = __float2half_rn(acc[jj]);
        }
        __syncthreads();
        // g_yt n-major: 128 n-rows x 8 j = 256 uint2, 1 per thread
        {
            int nn = tid >> 1, j4 = tid & 1;
            __half2 h0 = __floats2half2_rn(T[nn][j4 * 4], T[nn][j4 * 4 + 1]);
            __half2 h1 = __floats2half2_rn(T[nn][j4 * 4 + 2], T[nn][j4 * 4 + 3]);
            uint2 pk;
            pk.x = *reinterpret_cast<uint32_t*>(&h0);
            pk.y = *reinterpret_cast<uint32_t*>(&h1);
            *reinterpret_cast<uint2*>(&g_yt[(size_t)nn * NROWS + j0 + j4 * 4]) = pk;
        }
    } else {
        // ---- rowsum: dis = rsqrt(sum(A_row)+1) ----
        int row = blockIdx.x - ZBLK;
        const float4* r = A4 + (size_t)row * (NROWS / 4);
        float s = 0.f;
        #pragma unroll
        for (int p = 0; p < 8; p++) {
            float4 v = __ldcs(r + tid + p * 256);
            s += (v.x + v.y) + (v.z + v.w);
        }
        #pragma unroll
        for (int o = 16; o; o >>= 1) s += __shfl_xor_sync(0xffffffffu, s, o);
        if ((tid & 31) == 0) ws[tid >> 5] = s;
        __syncthreads();
        if (tid < 8) {
            float t = ws[tid];
            #pragma unroll
            for (int o = 4; o; o >>= 1) t += __shfl_xor_sync(0xffu, t, o);
            if (tid == 0) g_dis[row] = rsqrtf(t + 1.0f);
        }
    }
}

// ===================== kernel 2: split-K fp16 GEMM, dis folded into A conversion =====================
#define BM 256
#define BK 32
#define BSTGN 4
#define ASTR 40
#define AHSTG (BM * ASTR)
#define BSTR 40
#define BSTG (DIM * BSTR)
#define SMEM_BYTES ((2 * AHSTG + BSTGN * BSTG) * 2)  // 81920 B

static __device__ __forceinline__ void mma_f16(float* c, const uint32_t* a, const uint32_t* b) {
    asm volatile(
        "mma.sync.aligned.m16n8k16.row.col.f32.f16.f16.f32 "
        "{%0,%1,%2,%3}, {%4,%5,%6,%7}, {%8,%9}, {%0,%1,%2,%3};"
        : "+f"(c[0]), "+f"(c[1]), "+f"(c[2]), "+f"(c[3])
        : "r"(a[0]), "r"(a[1]), "r"(a[2]), "r"(a[3]), "r"(b[0]), "r"(b[1]));
}

static __device__ __forceinline__ void ldsm4(uint32_t* r, uint32_t addr) {
    asm volatile("ldmatrix.sync.aligned.m8n8.x4.shared.b16 {%0,%1,%2,%3}, [%4];"
                 : "=r"(r[0]), "=r"(r[1]), "=r"(r[2]), "=r"(r[3]) : "r"(addr));
}

__global__ void __launch_bounds__(256, 1) gemm_kernel(const float* __restrict__ A) {
    extern __shared__ __half smh[];
    __half* sAh = smh;                 // [2][AHSTG]
    __half* sB = smh + 2 * AHSTG;      // [BSTGN][BSTG]

    int tid = threadIdx.x, wid = tid >> 5, lane = tid & 31;
    int gid = lane >> 2, tig = lane & 3;
    const int m0 = blockIdx.x * BM;
    const int kbase = blockIdx.y * KSLICE;

    const int wm0 = (wid >> 1) * 64, wn0 = (wid & 1) * 64;

    float acc[4][8][4];
    #pragma unroll
    for (int mf = 0; mf < 4; mf++)
        #pragma unroll
        for (int nf = 0; nf < 8; nf++)
            #pragma unroll
            for (int q = 0; q < 4; q++) acc[mf][nf][q] = 0.f;

    const int a_row = lane & 15;
    const uint32_t a_koff = (uint32_t)(lane >> 4) * 16;
    const int b_row = (lane & 7) | ((lane >> 4) << 3);
    const uint32_t b_koff = (uint32_t)((lane >> 3) & 1) * 16;

    const int ar_r = tid >> 3, ar_c = tid & 7;
    float4 areg[8];
    float4 dis4;

    auto ldgA = [&](int stage) {
        int kk = kbase + stage * BK;
        const float* gp0 = A + (size_t)(m0 + ar_r) * NROWS + kk + ar_c * 4;
        dis4 = *reinterpret_cast<const float4*>(&g_dis[kk + ar_c * 4]);
        #pragma unroll
        for (int it = 0; it < 8; it++)
            areg[it] = __ldcs(reinterpret_cast<const float4*>(gp0 + (size_t)(it * 32) * NROWS));
    };
    auto stsA = [&](int slot) {
        __half* dst0 = sAh + slot * AHSTG + ar_r * ASTR + ar_c * 4;
        #pragma unroll
        for (int it = 0; it < 8; it++) {
            __half2 h0 = __floats2half2_rn(areg[it].x * dis4.x, areg[it].y * dis4.y);
            __half2 h1 = __floats2half2_rn(areg[it].z * dis4.z, areg[it].w * dis4.w);
            uint2 pk;
            pk.x = *reinterpret_cast<uint32_t*>(&h0);
            pk.y = *reinterpret_cast<uint32_t*>(&h1);
            *reinterpret_cast<uint2*>(dst0 + it * 32 * ASTR) = pk;
        }
    };
    auto issueB = [&](int stage, int buf) {
        int kk = kbase + stage * BK;
        #pragma unroll
        for (int it = 0; it < 2; it++) {
            int idx = it * 256 + tid;
            int r = idx >> 2, c = idx & 3;
            const __half* gp = g_yt + (size_t)r * NROWS + kk + c * 8;
            uint32_t sb = s2u(sB + buf * BSTG + r * BSTR + c * 8);
            asm volatile("cp.async.cg.shared.global [%0], [%1], 16;" :: "r"(sb), "l"(gp));
        }
        asm volatile("cp.async.commit_group;");
    };

    ldgA(0);
    issueB(0, 0); issueB(1, 1); issueB(2, 2);

    const int NS = KSLICE / BK;  // 64
    for (int i = 0; i < NS; i++) {
        stsA(i & 1);
        if (i + 1 < NS) ldgA(i + 1);
        asm volatile("cp.async.wait_group %0;" :: "n"(BSTGN - 2));
        __syncthreads();
        if (i + 3 < NS) issueB(i + 3, (i + 3) & (BSTGN - 1));

        uint32_t a_s = s2u(sAh + (i & 1) * AHSTG);
        uint32_t b_s = s2u(sB + (i & (BSTGN - 1)) * BSTG);

        #pragma unroll
        for (int ks = 0; ks < 2; ks++) {
            uint32_t k0h = ks * 16;
            uint32_t ar[4][4], br[4][4];
            #pragma unroll
            for (int mf = 0; mf < 4; mf++)
                ldsm4(ar[mf], a_s + 2u * ((wm0 + mf * 16 + a_row) * ASTR + k0h) + a_koff);
            #pragma unroll
            for (int t = 0; t < 4; t++)
                ldsm4(br[t], b_s + 2u * ((wn0 + t * 16 + b_row) * BSTR + k0h) + b_koff);
            #pragma unroll
            for (int mf = 0; mf < 4; mf++)
                #pragma unroll
                for (int t = 0; t < 4; t++) {
                    uint32_t bt0[2] = {br[t][0], br[t][1]};
                    uint32_t bt1[2] = {br[t][2], br[t][3]};
                    mma_f16(acc[mf][2 * t], ar[mf], bt0);
                    mma_f16(acc[mf][2 * t + 1], ar[mf], bt1);
                }
        }
    }

    __half* P = g_parth[blockIdx.y];
    #pragma unroll
    for (int mf = 0; mf < 4; mf++) {
        int r0 = m0 + wm0 + mf * 16 + gid;
        #pragma unroll
        for (int nf = 0; nf < 8; nf++) {
            int c = wn0 + nf * 8 + 2 * tig;
            __half2 p0 = __floats2half2_rn(acc[mf][nf][0], acc[mf][nf][1]);
            __half2 p1 = __floats2half2_rn(acc[mf][nf][2], acc[mf][nf][3]);
            *reinterpret_cast<__half2*>(&P[(size_t)r0 * DIM + c]) = p0;
            *reinterpret_cast<__half2*>(&P[(size_t)(r0 + 8) * DIM + c]) = p1;
        }
    }
}

// ===================== kernel 3: out = dis .* (sum P + dis .* Y) + b =====================
__global__ void __launch_bounds__(256) reduce_kernel(const float* __restrict__ bias,
                                                     float* __restrict__ out) {
    int idx = blockIdx.x * 256 + threadIdx.x;     // float4-out index
    int row = idx >> 5, n4 = idx & 31;
    uint2 p0 = *reinterpret_cast<const uint2*>(&g_parth[0][(size_t)idx * 4]);
    uint2 p1 = *reinterpret_cast<const uint2*>(&g_parth[1][(size_t)idx * 4]);
    uint2 p2 = *reinterpret_cast<const uint2*>(&g_parth[2][(size_t)idx * 4]);
    uint2 p3 = *reinterpret_cast<const uint2*>(&g_parth[3][(size_t)idx * 4]);
    uint2 yv = *reinterpret_cast<const uint2*>(&g_yh[(size_t)idx * 4]);
    float d = g_dis[row];
    float4 bb = __ldg(reinterpret_cast<const float4*>(bias) + n4);

    float2 a0 = __half22float2(*reinterpret_cast<__half2*>(&p0.x));
    float2 a1 = __half22float2(*reinterpret_cast<__half2*>(&p0.y));
    float2 b0 = __half22float2(*reinterpret_cast<__half2*>(&p1.x));
    float2 b1 = __half22float2(*reinterpret_cast<__half2*>(&p1.y));
    float2 c0 = __half22float2(*reinterpret_cast<__half2*>(&p2.x));
    float2 c1 = __half22float2(*reinterpret_cast<__half2*>(&p2.y));
    float2 e0 = __half22float2(*reinterpret_cast<__half2*>(&p3.x));
    float2 e1 = __half22float2(*reinterpret_cast<__half2*>(&p3.y));
    float2 y0 = __half22float2(*reinterpret_cast<__half2*>(&yv.x));
    float2 y1 = __half22float2(*reinterpret_cast<__half2*>(&yv.y));

    float4 o;
    o.x = d * (a0.x + b0.x + c0.x + e0.x + d * y0.x) + bb.x;
    o.y = d * (a0.y + b0.y + c0.y + e0.y + d * y0.y) + bb.y;
    o.z = d * (a1.x + b1.x + c1.x + e1.x + d * y1.x) + bb.z;
    o.w = d * (a1.y + b1.y + c1.y + e1.y + d * y1.y) + bb.w;
    reinterpret_cast<float4*>(out)[idx] = o;
}

// ===================== host =====================
extern "C" void kernel_launch(void* const* d_in, const int* in_sizes, int n_in,
                              void* d_out, int out_size) {
    const float* X = (const float*)d_in[0];
    const float* A = (const float*)d_in[1];
    const float* W = (const float*)d_in[2];
    const float* b = (const float*)d_in[3];
    float* out = (float*)d_out;

    prep_kernel<<<NROWS + ZBLK, 256>>>((const float4*)A, X, W);

    cudaFuncSetAttribute(gemm_kernel, cudaFuncAttributeMaxDynamicSharedMemorySize, SMEM_BYTES);
    gemm_kernel<<<dim3(NROWS / BM, KSPLIT), 256, SMEM_BYTES>>>(A);
    reduce_kernel<<<NROWS * DIM / 4 / 256, 256>>>(b, out);
}